// round 9
// baseline (speedup 1.0000x reference)
#include <cuda_runtime.h>
#include <cuda_bf16.h>
#include <cstdint>

// Problem constants: N=512, B=256, F=400, D=14, K=2
#define GS_B 256
#define GS_F 400
#define GS_BF (GS_B * GS_F)      // 102400 images
#define GS_D 14
#define GS_DD (GS_D * GS_D)      // 196 pixels/image
#define GS_K 2

#define U4_PER_IM (GS_DD / 4)    // 49 uint4 per image
#define NTB 256                  // threads per block (1 uint4 each)
#define N_U4 (GS_BF * U4_PER_IM) // 5,017,600 uint4 total
#define GRID (N_U4 / NTB)        // 19600 blocks (exact)
#define IMS_PER_BLK 7            // max distinct images a block touches

__device__ __forceinline__ float ex2f(float x) {
    float y;
    asm("ex2.approx.f32 %0, %1;" : "=f"(y) : "f"(x));
    return y;
}

// Single fused kernel, no staging: thread = 4 consecutive flattened pixels
// (one uint4), direct Gaussian eval in log2 domain, one STG.128.
__global__ __launch_bounds__(NTB) void gs_direct(
    const int*          __restrict__ batch_idx,   // (B,)
    const unsigned int* __restrict__ m_mask,      // (B,F,K)
    const float*        __restrict__ height,      // (B,F,K)
    const float*        __restrict__ width,       // (B,F,K)
    const float*        __restrict__ x0,          // (B,F,K)
    const float*        __restrict__ y0,          // (B,F,K)
    const float*        __restrict__ background,  // (B,F)
    const float*        __restrict__ target_locs, // (N,F,2)
    float*              __restrict__ out)         // (B,F,D,D)
{
    // per-spot digest: (sx, sy, aL, l2c);  l2c = log2(h/(2*pi*w^2)), aL = -log2e/(2w^2)
    __shared__ float4 sparam[IMS_PER_BLK][GS_K];
    __shared__ float  sbg[IMS_PER_BLK];

    const int t    = threadIdx.x;
    const int wid  = t >> 5;
    const int lane = t & 31;

    const int u0       = blockIdx.x * NTB;        // first uint4 of block
    const int first_im = u0 / U4_PER_IM;

    // ---- Phase A: 14 digests on lanes (0,1) of warps 0..6; bg on warp 7 ----
    if (wid < IMS_PER_BLK && lane < GS_K) {
        const int im = min(first_im + wid, GS_BF - 1);
        const int k  = lane;
        const int b  = im / GS_F;
        const int f  = im - b * GS_F;

        const int   bi  = __ldg(&batch_idx[b]);
        const int   tlo = (bi * GS_F + f) * 2;
        const float tlx = __ldg(&target_locs[tlo]);
        const float tly = __ldg(&target_locs[tlo + 1]);

        const int i = im * GS_K + k;
        const unsigned int m = __ldg(&m_mask[i]);
        const float h = (m != 0u) ? __ldg(&height[i]) : 0.0f;
        const float w = __ldg(&width[i]);
        const float invw2 = __fdividef(1.0f, w * w);

        const float HALF_LOG2E = 0.7213475204444817f;   // 0.5*log2(e)
        const float INV_2PI    = 0.15915494309189535f;

        const float aL  = -HALF_LOG2E * invw2;
        const float l2c = __log2f(h * INV_2PI * invw2); // h==0 -> -inf -> e==0
        const float sx  = tlx + __ldg(&x0[i]);
        const float sy  = tly + __ldg(&y0[i]);

        sparam[wid][k] = make_float4(sx, sy, aL, l2c);
    }
    if (wid == 7 && lane < IMS_PER_BLK) {
        const int im = min(first_im + lane, GS_BF - 1);
        sbg[lane] = __ldg(&background[im]);
    }
    __syncthreads();

    // ---- Phase B: direct evaluation of 4 pixels ----
    const int eg  = u0 + t;                 // global uint4 index
    const int im  = eg / U4_PER_IM;         // magic-multiply division
    const int il  = im - first_im;          // 0..6
    const int rem = eg - im * U4_PER_IM;    // uint4 within image, 0..48
    const int i0  = rem * 4;                // first flattened pixel, 0..192

    float fpx = (float)(i0 / GS_D);
    float fpy = (float)(i0 - (i0 / GS_D) * GS_D);

    const float4 s0 = sparam[il][0];
    const float4 s1 = sparam[il][1];
    const float  bg = sbg[il];

    float acc[4];
#pragma unroll
    for (int q = 0; q < 4; ++q) {
        const float dx0 = fpx - s0.x;
        const float dy0 = fpy - s0.y;
        const float e0  = ex2f(fmaf(s0.z, fmaf(dx0, dx0, dy0 * dy0), s0.w));
        const float dx1 = fpx - s1.x;
        const float dy1 = fpy - s1.y;
        const float e1  = ex2f(fmaf(s1.z, fmaf(dx1, dx1, dy1 * dy1), s1.w));
        acc[q] = bg + e0 + e1;
        // advance flattened pixel: y++ with row wrap (D=14)
        fpy += 1.0f;
        if (fpy > 13.5f) { fpy = 0.0f; fpx += 1.0f; }
    }

    float4 r = make_float4(acc[0], acc[1], acc[2], acc[3]);
    reinterpret_cast<float4*>(out)[eg] = r;
}

extern "C" void kernel_launch(void* const* d_in, const int* in_sizes, int n_in,
                              void* d_out, int out_size) {
    const int*          batch_idx   = (const int*)d_in[0];
    const unsigned int* m_mask      = (const unsigned int*)d_in[1];
    const float*        height      = (const float*)d_in[2];
    const float*        width       = (const float*)d_in[3];
    const float*        x0          = (const float*)d_in[4];
    const float*        y0          = (const float*)d_in[5];
    const float*        background  = (const float*)d_in[6];
    const float*        target_locs = (const float*)d_in[7];
    // d_in[8] = pixel_pos: integer grid, regenerated analytically

    float* out = (float*)d_out;

    gs_direct<<<GRID, NTB>>>(batch_idx, m_mask, height, width,
                             x0, y0, background, target_locs, out);
}